// round 5
// baseline (speedup 1.0000x reference)
#include <cuda_runtime.h>
#include <cstdint>

#define TPB 256

__device__ __forceinline__ float4 ldcs4(const float4* p) { return __ldcs(p); }
__device__ __forceinline__ void stcs4(float4* p, float4 v) { __stcs(p, v); }

// Full compute for one pair, result via pointers (used by tail path)
__device__ __forceinline__ void tp_compute(
    float a, float b, const float* u, const float* v,
    const float* A, const float* B,
    float& z0, float* z1, float* z2)
{
    z0 = a * b;
    #pragma unroll
    for (int i = 0; i < 3; i++) z0 = fmaf(u[i], v[i], z0);
    #pragma unroll
    for (int i = 0; i < 9; i++) z0 = fmaf(A[i], B[i], z0);
    #pragma unroll
    for (int i = 0; i < 3; i++) {
        float s = fmaf(a, v[i], b * u[i]);
        #pragma unroll
        for (int d = 0; d < 3; d++) {
            s = fmaf(u[d], B[d * 3 + i], s);
            s = fmaf(A[i * 3 + d], v[d], s);
        }
        z1[i] = s;
    }
    #pragma unroll
    for (int i = 0; i < 3; i++)
        #pragma unroll
        for (int j = 0; j < 3; j++) {
            float s = fmaf(a, B[i * 3 + j], b * A[i * 3 + j]);
            s = fmaf(u[i], v[j], s);
            #pragma unroll
            for (int k = 0; k < 3; k++)
                s = fmaf(A[i * 3 + k], B[k * 3 + j], s);
            z2[i * 3 + j] = s;
        }
}

__global__ __launch_bounds__(TPB, 8) void tp_kernel(
    const float* __restrict__ x0, const float* __restrict__ y0,
    const float* __restrict__ x1, const float* __restrict__ y1,
    const float* __restrict__ x2, const float* __restrict__ y2,
    float* __restrict__ out, long long NC)
{
    __shared__ float sA[TPB * 9];
    __shared__ float sB[TPB * 9];
    __shared__ float su[TPB * 3];
    __shared__ float sv[TPB * 3];
    __shared__ float sa[TPB];
    __shared__ float sb[TPB];

    const long long base = (long long)blockIdx.x * TPB;
    const int t = threadIdx.x;
    long long rem = NC - base;
    const int npair = rem < TPB ? (int)rem : TPB;
    const bool full = (npair == TPB);

    // ---- Stage inputs into smem: coalesced float4 streaming loads ----
    if (full) {
        {
            const float4* gA = (const float4*)(x2 + base * 9);
            const float4* gB = (const float4*)(y2 + base * 9);
            float4* s4a = (float4*)sA;
            float4* s4b = (float4*)sB;
            #pragma unroll
            for (int i = t; i < TPB * 9 / 4; i += TPB) { s4a[i] = ldcs4(gA + i); s4b[i] = ldcs4(gB + i); }
        }
        {
            const float4* gu = (const float4*)(x1 + base * 3);
            const float4* gv = (const float4*)(y1 + base * 3);
            float4* s4u = (float4*)su;
            float4* s4v = (float4*)sv;
            #pragma unroll
            for (int i = t; i < TPB * 3 / 4; i += TPB) { s4u[i] = ldcs4(gu + i); s4v[i] = ldcs4(gv + i); }
        }
        {
            const float4* ga = (const float4*)(x0 + base);
            const float4* gb = (const float4*)(y0 + base);
            float4* s4a = (float4*)sa;
            float4* s4b = (float4*)sb;
            if (t < TPB / 4) { s4a[t] = ldcs4(ga + t); s4b[t] = ldcs4(gb + t); }
        }
    } else {
        for (int i = t; i < npair * 9; i += TPB) { sA[i] = x2[base * 9 + i]; sB[i] = y2[base * 9 + i]; }
        for (int i = t; i < npair * 3; i += TPB) { su[i] = x1[base * 3 + i]; sv[i] = y1[base * 3 + i]; }
        for (int i = t; i < npair;     i += TPB) { sa[i] = x0[base + i];     sb[i] = y0[base + i]; }
    }
    __syncthreads();

    // ---- Per-pair compute, writing results straight back into this thread's
    //      own smem slots (no cross-thread hazard: slot t is only ever touched
    //      by thread t between the two barriers). Accumulators die early ->
    //      low register pressure -> 8 blocks/SM. ----
    if (t < npair) {
        const float a = sa[t], b = sb[t];
        float u[3], v[3], A[9], B[9];
        #pragma unroll
        for (int i = 0; i < 3; i++) { u[i] = su[t * 3 + i]; v[i] = sv[t * 3 + i]; }
        #pragma unroll
        for (int i = 0; i < 9; i++) { A[i] = sA[t * 9 + i]; B[i] = sB[t * 9 + i]; }

        // z2 rows -> sA[t*9+..]
        #pragma unroll
        for (int i = 0; i < 3; i++) {
            #pragma unroll
            for (int j = 0; j < 3; j++) {
                float s = fmaf(a, B[i * 3 + j], b * A[i * 3 + j]);
                s = fmaf(u[i], v[j], s);
                #pragma unroll
                for (int k = 0; k < 3; k++)
                    s = fmaf(A[i * 3 + k], B[k * 3 + j], s);
                sA[t * 9 + i * 3 + j] = s;
            }
        }
        // z1 -> su[t*3+..]
        #pragma unroll
        for (int i = 0; i < 3; i++) {
            float s = fmaf(a, v[i], b * u[i]);
            #pragma unroll
            for (int d = 0; d < 3; d++) {
                s = fmaf(u[d], B[d * 3 + i], s);
                s = fmaf(A[i * 3 + d], v[d], s);
            }
            su[t * 3 + i] = s;
        }
        // z0 -> sa[t]
        float z0 = a * b;
        #pragma unroll
        for (int i = 0; i < 3; i++) z0 = fmaf(u[i], v[i], z0);
        #pragma unroll
        for (int i = 0; i < 9; i++) z0 = fmaf(A[i], B[i], z0);
        sa[t] = z0;
    }
    __syncthreads();

    // ---- Coalesced streaming stores ----
    float* o0 = out;
    float* o1 = out + NC;
    float* o2 = out + 4 * NC;
    if (full) {
        float4* g0 = (float4*)(o0 + base);
        float4* g1 = (float4*)(o1 + base * 3);
        float4* g2 = (float4*)(o2 + base * 9);
        const float4* s40 = (const float4*)sa;
        const float4* s41 = (const float4*)su;
        const float4* s42 = (const float4*)sA;
        if (t < TPB / 4) stcs4(g0 + t, s40[t]);
        #pragma unroll
        for (int i = t; i < TPB * 3 / 4; i += TPB) stcs4(g1 + i, s41[i]);
        #pragma unroll
        for (int i = t; i < TPB * 9 / 4; i += TPB) stcs4(g2 + i, s42[i]);
    } else {
        for (int i = t; i < npair;     i += TPB) o0[base + i]     = sa[i];
        for (int i = t; i < npair * 3; i += TPB) o1[base * 3 + i] = su[i];
        for (int i = t; i < npair * 9; i += TPB) o2[base * 9 + i] = sA[i];
    }
}

extern "C" void kernel_launch(void* const* d_in, const int* in_sizes, int n_in,
                              void* d_out, int out_size)
{
    // out = (z0, z1, z2) concatenated: 13*NC floats
    const long long NC = (long long)out_size / 13;

    // Classify inputs by element count; x precedes y within each size class
    // in both plausible metadata orderings.
    const float *x0 = nullptr, *y0 = nullptr, *x1 = nullptr, *y1 = nullptr,
                *x2 = nullptr, *y2 = nullptr;
    for (int i = 0; i < n_in; i++) {
        long long s = in_sizes[i];
        const float* p = (const float*)d_in[i];
        if (s == NC)          { if (!x0) x0 = p; else y0 = p; }
        else if (s == 3 * NC) { if (!x1) x1 = p; else y1 = p; }
        else if (s == 9 * NC) { if (!x2) x2 = p; else y2 = p; }
    }

    const int nblocks = (int)((NC + TPB - 1) / TPB);
    tp_kernel<<<nblocks, TPB>>>(x0, y0, x1, y1, x2, y2, (float*)d_out, NC);
}

// round 6
// speedup vs baseline: 1.2570x; 1.2570x over previous
#include <cuda_runtime.h>
#include <cstdint>

#define TPB 256

__device__ __forceinline__ float4 ldcs4(const float4* p) { return __ldcs(p); }
__device__ __forceinline__ void stcs4(float4* p, float4 v) { __stcs(p, v); }

__device__ __forceinline__ void tp_compute(
    float a, float b, const float* u, const float* v,
    const float* A, const float* B,
    float& z0, float* z1, float* z2)
{
    z0 = a * b;
    #pragma unroll
    for (int i = 0; i < 3; i++) z0 = fmaf(u[i], v[i], z0);
    #pragma unroll
    for (int i = 0; i < 9; i++) z0 = fmaf(A[i], B[i], z0);
    #pragma unroll
    for (int i = 0; i < 3; i++) {
        float s = fmaf(a, v[i], b * u[i]);
        #pragma unroll
        for (int d = 0; d < 3; d++) {
            s = fmaf(u[d], B[d * 3 + i], s);
            s = fmaf(A[i * 3 + d], v[d], s);
        }
        z1[i] = s;
    }
    #pragma unroll
    for (int i = 0; i < 3; i++)
        #pragma unroll
        for (int j = 0; j < 3; j++) {
            float s = fmaf(a, B[i * 3 + j], b * A[i * 3 + j]);
            s = fmaf(u[i], v[j], s);
            #pragma unroll
            for (int k = 0; k < 3; k++)
                s = fmaf(A[i * 3 + k], B[k * 3 + j], s);
            z2[i * 3 + j] = s;
        }
}

__global__ __launch_bounds__(TPB) void tp_kernel(
    const float* __restrict__ x0, const float* __restrict__ y0,
    const float* __restrict__ x1, const float* __restrict__ y1,
    const float* __restrict__ x2, const float* __restrict__ y2,
    float* __restrict__ out, long long NC)
{
    __shared__ float sA[TPB * 9];
    __shared__ float sB[TPB * 9];
    __shared__ float su[TPB * 3];
    __shared__ float sv[TPB * 3];
    __shared__ float sa[TPB];
    __shared__ float sb[TPB];

    const long long base = (long long)blockIdx.x * TPB;
    const int t = threadIdx.x;
    long long rem = NC - base;
    const int npair = rem < TPB ? (int)rem : TPB;
    const bool full = (npair == TPB);

    if (full) {
        // ---- Front-batched staging: issue ALL global loads into registers
        //      first (MLP ~10 per thread), then drain to smem. Predicates are
        //      warp-uniform (t<64 = warps 0-1, t<192 = warps 0-5). ----
        const float4* gA = (const float4*)(x2 + base * 9);   // 576 float4
        const float4* gB = (const float4*)(y2 + base * 9);   // 576 float4
        const float4* gu = (const float4*)(x1 + base * 3);   // 192 float4
        const float4* gv = (const float4*)(y1 + base * 3);   // 192 float4
        const float4* ga = (const float4*)(x0 + base);       //  64 float4
        const float4* gb = (const float4*)(y0 + base);       //  64 float4

        const bool m3 = (t < 64);
        const bool mv = (t < 192);

        float4 rA0 = ldcs4(gA + t);
        float4 rB0 = ldcs4(gB + t);
        float4 rA1 = ldcs4(gA + t + 256);
        float4 rB1 = ldcs4(gB + t + 256);
        float4 rA2, rB2, ra, rb, ru, rv;
        if (m3) {
            rA2 = ldcs4(gA + t + 512);
            rB2 = ldcs4(gB + t + 512);
            ra  = ldcs4(ga + t);
            rb  = ldcs4(gb + t);
        }
        if (mv) {
            ru = ldcs4(gu + t);
            rv = ldcs4(gv + t);
        }

        float4* s4A = (float4*)sA;
        float4* s4B = (float4*)sB;
        float4* s4u = (float4*)su;
        float4* s4v = (float4*)sv;
        float4* s4a = (float4*)sa;
        float4* s4b = (float4*)sb;
        s4A[t]       = rA0;
        s4B[t]       = rB0;
        s4A[t + 256] = rA1;
        s4B[t + 256] = rB1;
        if (m3) {
            s4A[t + 512] = rA2;
            s4B[t + 512] = rB2;
            s4a[t] = ra;
            s4b[t] = rb;
        }
        if (mv) {
            s4u[t] = ru;
            s4v[t] = rv;
        }
    } else {
        for (int i = t; i < npair * 9; i += TPB) { sA[i] = x2[base * 9 + i]; sB[i] = y2[base * 9 + i]; }
        for (int i = t; i < npair * 3; i += TPB) { su[i] = x1[base * 3 + i]; sv[i] = y1[base * 3 + i]; }
        for (int i = t; i < npair;     i += TPB) { sa[i] = x0[base + i];     sb[i] = y0[base + i]; }
    }
    __syncthreads();

    // ---- Per-pair compute (smem strides 9/3/1 words: conflict-free) ----
    float z0 = 0.f, z1[3], z2[9];
    if (t < npair) {
        float a = sa[t], b = sb[t];
        float u[3], v[3], A[9], B[9];
        #pragma unroll
        for (int i = 0; i < 3; i++) { u[i] = su[t * 3 + i]; v[i] = sv[t * 3 + i]; }
        #pragma unroll
        for (int i = 0; i < 9; i++) { A[i] = sA[t * 9 + i]; B[i] = sB[t * 9 + i]; }
        tp_compute(a, b, u, v, A, B, z0, z1, z2);
    }
    __syncthreads();

    // ---- Stash results in smem (reuse buffers), then coalesced streaming stores ----
    if (t < npair) {
        sa[t] = z0;
        #pragma unroll
        for (int i = 0; i < 3; i++) su[t * 3 + i] = z1[i];
        #pragma unroll
        for (int i = 0; i < 9; i++) sA[t * 9 + i] = z2[i];
    }
    __syncthreads();

    float* o0 = out;
    float* o1 = out + NC;
    float* o2 = out + 4 * NC;
    if (full) {
        float4* g0 = (float4*)(o0 + base);
        float4* g1 = (float4*)(o1 + base * 3);
        float4* g2 = (float4*)(o2 + base * 9);
        const float4* s40 = (const float4*)sa;
        const float4* s41 = (const float4*)su;
        const float4* s42 = (const float4*)sA;
        if (t < TPB / 4) stcs4(g0 + t, s40[t]);
        #pragma unroll
        for (int i = t; i < TPB * 3 / 4; i += TPB) stcs4(g1 + i, s41[i]);
        #pragma unroll
        for (int i = t; i < TPB * 9 / 4; i += TPB) stcs4(g2 + i, s42[i]);
    } else {
        for (int i = t; i < npair;     i += TPB) o0[base + i]     = sa[i];
        for (int i = t; i < npair * 3; i += TPB) o1[base * 3 + i] = su[i];
        for (int i = t; i < npair * 9; i += TPB) o2[base * 9 + i] = sA[i];
    }
}

extern "C" void kernel_launch(void* const* d_in, const int* in_sizes, int n_in,
                              void* d_out, int out_size)
{
    // out = (z0, z1, z2) concatenated: 13*NC floats
    const long long NC = (long long)out_size / 13;

    // Classify inputs by element count; x precedes y within each size class
    // in both plausible metadata orderings.
    const float *x0 = nullptr, *y0 = nullptr, *x1 = nullptr, *y1 = nullptr,
                *x2 = nullptr, *y2 = nullptr;
    for (int i = 0; i < n_in; i++) {
        long long s = in_sizes[i];
        const float* p = (const float*)d_in[i];
        if (s == NC)          { if (!x0) x0 = p; else y0 = p; }
        else if (s == 3 * NC) { if (!x1) x1 = p; else y1 = p; }
        else if (s == 9 * NC) { if (!x2) x2 = p; else y2 = p; }
    }

    const int nblocks = (int)((NC + TPB - 1) / TPB);
    tp_kernel<<<nblocks, TPB>>>(x0, y0, x1, y1, x2, y2, (float*)d_out, NC);
}

// round 7
// speedup vs baseline: 1.2659x; 1.0071x over previous
#include <cuda_runtime.h>
#include <cstdint>

#define TPB 256

__device__ __forceinline__ float4 ldcs4(const float4* p) { return __ldcs(p); }
__device__ __forceinline__ void stcs4(float4* p, float4 v) { __stcs(p, v); }

// Used by the (never-taken for NC%256==0) tail path
__device__ __forceinline__ void tp_compute(
    float a, float b, const float* u, const float* v,
    const float* A, const float* B,
    float& z0, float* z1, float* z2)
{
    z0 = a * b;
    #pragma unroll
    for (int i = 0; i < 3; i++) z0 = fmaf(u[i], v[i], z0);
    #pragma unroll
    for (int i = 0; i < 9; i++) z0 = fmaf(A[i], B[i], z0);
    #pragma unroll
    for (int i = 0; i < 3; i++) {
        float s = fmaf(a, v[i], b * u[i]);
        #pragma unroll
        for (int d = 0; d < 3; d++) {
            s = fmaf(u[d], B[d * 3 + i], s);
            s = fmaf(A[i * 3 + d], v[d], s);
        }
        z1[i] = s;
    }
    #pragma unroll
    for (int i = 0; i < 3; i++)
        #pragma unroll
        for (int j = 0; j < 3; j++) {
            float s = fmaf(a, B[i * 3 + j], b * A[i * 3 + j]);
            s = fmaf(u[i], v[j], s);
            #pragma unroll
            for (int k = 0; k < 3; k++)
                s = fmaf(A[i * 3 + k], B[k * 3 + j], s);
            z2[i * 3 + j] = s;
        }
}

__global__ __launch_bounds__(TPB) void tp_kernel(
    const float* __restrict__ x0, const float* __restrict__ y0,
    const float* __restrict__ x1, const float* __restrict__ y1,
    const float* __restrict__ x2, const float* __restrict__ y2,
    float* __restrict__ out, long long NC)
{
    __shared__ float sA[TPB * 9];
    __shared__ float sB[TPB * 9];
    __shared__ float su[TPB * 3];
    __shared__ float sv[TPB * 3];
    __shared__ float sa[TPB];
    __shared__ float sb[TPB];

    const long long base = (long long)blockIdx.x * TPB;
    const int t = threadIdx.x;
    long long rem = NC - base;
    const int npair = rem < TPB ? (int)rem : TPB;
    const bool full = (npair == TPB);

    if (full) {
        // ---- Front-batched staging: issue ALL global loads into registers
        //      first (MLP ~10 per thread), then drain to smem. Predicates are
        //      warp-uniform (t<64 = warps 0-1, t<192 = warps 0-5). ----
        const float4* gA = (const float4*)(x2 + base * 9);   // 576 float4
        const float4* gB = (const float4*)(y2 + base * 9);   // 576 float4
        const float4* gu = (const float4*)(x1 + base * 3);   // 192 float4
        const float4* gv = (const float4*)(y1 + base * 3);   // 192 float4
        const float4* ga = (const float4*)(x0 + base);       //  64 float4
        const float4* gb = (const float4*)(y0 + base);       //  64 float4

        const bool m3 = (t < 64);
        const bool mv = (t < 192);

        float4 rA0 = ldcs4(gA + t);
        float4 rB0 = ldcs4(gB + t);
        float4 rA1 = ldcs4(gA + t + 256);
        float4 rB1 = ldcs4(gB + t + 256);
        float4 rA2, rB2, ra, rb, ru, rv;
        if (m3) {
            rA2 = ldcs4(gA + t + 512);
            rB2 = ldcs4(gB + t + 512);
            ra  = ldcs4(ga + t);
            rb  = ldcs4(gb + t);
        }
        if (mv) {
            ru = ldcs4(gu + t);
            rv = ldcs4(gv + t);
        }

        float4* s4A = (float4*)sA;
        float4* s4B = (float4*)sB;
        float4* s4u = (float4*)su;
        float4* s4v = (float4*)sv;
        float4* s4a = (float4*)sa;
        float4* s4b = (float4*)sb;
        s4A[t]       = rA0;
        s4B[t]       = rB0;
        s4A[t + 256] = rA1;
        s4B[t + 256] = rB1;
        if (m3) {
            s4A[t + 512] = rA2;
            s4B[t + 512] = rB2;
            s4a[t] = ra;
            s4b[t] = rb;
        }
        if (mv) {
            s4u[t] = ru;
            s4v[t] = rv;
        }
    } else {
        for (int i = t; i < npair * 9; i += TPB) { sA[i] = x2[base * 9 + i]; sB[i] = y2[base * 9 + i]; }
        for (int i = t; i < npair * 3; i += TPB) { su[i] = x1[base * 3 + i]; sv[i] = y1[base * 3 + i]; }
        for (int i = t; i < npair;     i += TPB) { sa[i] = x0[base + i];     sb[i] = y0[base + i]; }
    }
    __syncthreads();

    // ---- Per-pair compute. Operands pulled fully into registers, then
    //      results written straight back into this thread's OWN smem slots
    //      (slot t touched only by thread t between the two barriers) ->
    //      middle barrier eliminated. No launch_bounds cap: keep regs free
    //      so the front-batch MLP survives (R5 lesson). ----
    if (t < npair) {
        const float a = sa[t], b = sb[t];
        float u[3], v[3], A[9], B[9];
        #pragma unroll
        for (int i = 0; i < 3; i++) { u[i] = su[t * 3 + i]; v[i] = sv[t * 3 + i]; }
        #pragma unroll
        for (int i = 0; i < 9; i++) { A[i] = sA[t * 9 + i]; B[i] = sB[t * 9 + i]; }

        // z2 -> sA[t*9+..]
        #pragma unroll
        for (int i = 0; i < 3; i++) {
            #pragma unroll
            for (int j = 0; j < 3; j++) {
                float s = fmaf(a, B[i * 3 + j], b * A[i * 3 + j]);
                s = fmaf(u[i], v[j], s);
                #pragma unroll
                for (int k = 0; k < 3; k++)
                    s = fmaf(A[i * 3 + k], B[k * 3 + j], s);
                sA[t * 9 + i * 3 + j] = s;
            }
        }
        // z1 -> su[t*3+..]
        #pragma unroll
        for (int i = 0; i < 3; i++) {
            float s = fmaf(a, v[i], b * u[i]);
            #pragma unroll
            for (int d = 0; d < 3; d++) {
                s = fmaf(u[d], B[d * 3 + i], s);
                s = fmaf(A[i * 3 + d], v[d], s);
            }
            su[t * 3 + i] = s;
        }
        // z0 -> sa[t]
        float z0 = a * b;
        #pragma unroll
        for (int i = 0; i < 3; i++) z0 = fmaf(u[i], v[i], z0);
        #pragma unroll
        for (int i = 0; i < 9; i++) z0 = fmaf(A[i], B[i], z0);
        sa[t] = z0;
    }
    __syncthreads();

    // ---- Coalesced streaming stores ----
    float* o0 = out;
    float* o1 = out + NC;
    float* o2 = out + 4 * NC;
    if (full) {
        float4* g0 = (float4*)(o0 + base);
        float4* g1 = (float4*)(o1 + base * 3);
        float4* g2 = (float4*)(o2 + base * 9);
        const float4* s40 = (const float4*)sa;
        const float4* s41 = (const float4*)su;
        const float4* s42 = (const float4*)sA;
        if (t < TPB / 4) stcs4(g0 + t, s40[t]);
        #pragma unroll
        for (int i = t; i < TPB * 3 / 4; i += TPB) stcs4(g1 + i, s41[i]);
        #pragma unroll
        for (int i = t; i < TPB * 9 / 4; i += TPB) stcs4(g2 + i, s42[i]);
    } else {
        for (int i = t; i < npair;     i += TPB) o0[base + i]     = sa[i];
        for (int i = t; i < npair * 3; i += TPB) o1[base * 3 + i] = su[i];
        for (int i = t; i < npair * 9; i += TPB) o2[base * 9 + i] = sA[i];
    }
}

extern "C" void kernel_launch(void* const* d_in, const int* in_sizes, int n_in,
                              void* d_out, int out_size)
{
    // out = (z0, z1, z2) concatenated: 13*NC floats
    const long long NC = (long long)out_size / 13;

    // Classify inputs by element count; x precedes y within each size class
    // in both plausible metadata orderings.
    const float *x0 = nullptr, *y0 = nullptr, *x1 = nullptr, *y1 = nullptr,
                *x2 = nullptr, *y2 = nullptr;
    for (int i = 0; i < n_in; i++) {
        long long s = in_sizes[i];
        const float* p = (const float*)d_in[i];
        if (s == NC)          { if (!x0) x0 = p; else y0 = p; }
        else if (s == 3 * NC) { if (!x1) x1 = p; else y1 = p; }
        else if (s == 9 * NC) { if (!x2) x2 = p; else y2 = p; }
    }

    const int nblocks = (int)((NC + TPB - 1) / TPB);
    tp_kernel<<<nblocks, TPB>>>(x0, y0, x1, y1, x2, y2, (float*)d_out, NC);
}